// round 2
// baseline (speedup 1.0000x reference)
#include <cuda_runtime.h>

#define NB 64
#define NT 256
#define NC 2048
#define NH 512
#define NO 11
#define THRESH 1.0f
#define LEAKV  0.003f
#define OLEAK  0.0015f

// Scratch (static device allocations — allowed)
__device__ float g_Iin[NB * NT * NH];      // [b][t][h] = x @ w1^T
__device__ float g_WrecT[NH * NH];         // [j][h] = w_rec[h][j]

// ---------------------------------------------------------------------------
// Prep: transpose w_rec so that "add row j" is a coalesced read.
// ---------------------------------------------------------------------------
__global__ void prep_kernel(const float* __restrict__ w_rec) {
    int idx = blockIdx.x * blockDim.x + threadIdx.x;
    if (idx < NH * NH) {
        int h = idx / NH, j = idx % NH;        // coalesced read of w_rec[h][j]
        g_WrecT[j * NH + h] = w_rec[idx];
    }
}

// ---------------------------------------------------------------------------
// Big GEMM: Iin[M,N] = x[M,K] @ w1[N,K]^T   (M=16384, N=512, K=2048), fp32
// 128x128 block tile, BK=8, 8x8 per thread, 256 threads.
// ---------------------------------------------------------------------------
#define BM 128
#define BN 128
#define BKK 8
#define TM 8
#define TN 8

__global__ __launch_bounds__(256) void gemm_kernel(
    const float* __restrict__ A,    // x  [M,K]
    const float* __restrict__ W)    // w1 [N,K]
{
    const int K = NC;
    __shared__ float As[BKK][BM];
    __shared__ float Bs[BKK][BN];

    const int tid  = threadIdx.x;
    const int trow = tid / (BN / TN);   // 0..15
    const int tcol = tid % (BN / TN);   // 0..15
    const int lrow = tid >> 1;          // 0..127
    const int lcol = (tid & 1) * 4;     // 0 or 4

    const float* Ab = A + (size_t)blockIdx.y * BM * K + (size_t)lrow * K + lcol;
    const float* Wb = W + (size_t)blockIdx.x * BN * K + (size_t)lrow * K + lcol;

    float acc[TM][TN] = {};
    float af[TM], bf[TN];

    for (int k0 = 0; k0 < K; k0 += BKK) {
        float4 av = *(const float4*)(Ab + k0);
        float4 wv = *(const float4*)(Wb + k0);
        As[lcol + 0][lrow] = av.x;
        As[lcol + 1][lrow] = av.y;
        As[lcol + 2][lrow] = av.z;
        As[lcol + 3][lrow] = av.w;
        Bs[lcol + 0][lrow] = wv.x;
        Bs[lcol + 1][lrow] = wv.y;
        Bs[lcol + 2][lrow] = wv.z;
        Bs[lcol + 3][lrow] = wv.w;
        __syncthreads();

        #pragma unroll
        for (int k = 0; k < BKK; ++k) {
            #pragma unroll
            for (int m = 0; m < TM; m += 4) {
                float4 t = *(const float4*)&As[k][trow * TM + m];
                af[m] = t.x; af[m + 1] = t.y; af[m + 2] = t.z; af[m + 3] = t.w;
            }
            #pragma unroll
            for (int n = 0; n < TN; n += 4) {
                float4 t = *(const float4*)&Bs[k][tcol * TN + n];
                bf[n] = t.x; bf[n + 1] = t.y; bf[n + 2] = t.z; bf[n + 3] = t.w;
            }
            #pragma unroll
            for (int m = 0; m < TM; ++m)
                #pragma unroll
                for (int n = 0; n < TN; ++n)
                    acc[m][n] = fmaf(af[m], bf[n], acc[m][n]);
        }
        __syncthreads();
    }

    float* Cb = g_Iin + ((size_t)blockIdx.y * BM + trow * TM) * NH
                      + blockIdx.x * BN + tcol * TN;
    #pragma unroll
    for (int m = 0; m < TM; ++m) {
        #pragma unroll
        for (int n = 0; n < TN; n += 4) {
            *(float4*)(Cb + (size_t)m * NH + n) =
                make_float4(acc[m][n], acc[m][n + 1], acc[m][n + 2], acc[m][n + 3]);
        }
    }
}

// ---------------------------------------------------------------------------
// Sequential SNN: one CTA per batch element, one thread per hidden neuron.
// Recurrence handled spike-sparsely: ballot -> compact active list in smem ->
// each thread h accumulates WrecT[j][h] over active j (L2-resident, coalesced).
// Output neurons (O=11) handled by threads 0..10 from smem-transposed w2.
// ---------------------------------------------------------------------------
__global__ __launch_bounds__(512) void snn_kernel(
    const float* __restrict__ w2,   // [O,H]
    float* __restrict__ out)        // [B,O]
{
    const int b    = blockIdx.x;
    const int h    = threadIdx.x;
    const int lane = h & 31;
    const int warp = h >> 5;

    __shared__ int   s_list[NH];
    __shared__ int   s_wcnt[16];
    __shared__ int   s_base[16];
    __shared__ int   s_total;
    __shared__ float s_w2t[NH * 12];   // [j][o], padded stride 12 (conflict-free)

    // Stage w2 transposed into smem (coalesced global reads)
    #pragma unroll
    for (int o = 0; o < NO; ++o)
        s_w2t[h * 12 + o] = w2[o * NH + h];

    float v1 = 0.f, rec = 0.f, v2 = 0.f, osum = 0.f;
    const float* Iin_b = g_Iin + (size_t)b * NT * NH + h;

    __syncthreads();
    float iin = Iin_b[0];   // prefetch t=0

    for (int t = 0; t < NT; ++t) {
        // LIF update (matches reference: v1 += i1 - LEAK; subtractive reset)
        v1 += iin + rec - LEAKV;
        bool spike = (v1 >= THRESH);
        if (spike) v1 -= THRESH;

        // Compact active-spike list
        unsigned m = __ballot_sync(0xffffffffu, spike);
        if (lane == 0) s_wcnt[warp] = __popc(m);
        __syncthreads();
        if (h == 0) {
            int s = 0;
            #pragma unroll
            for (int w = 0; w < 16; ++w) { s_base[w] = s; s += s_wcnt[w]; }
            s_total = s;
        }
        __syncthreads();
        if (spike)
            s_list[s_base[warp] + __popc(m & ((1u << lane) - 1u))] = h;
        __syncthreads();

        const int total = s_total;

        // Prefetch next timestep's input current (hide DRAM latency)
        if (t + 1 < NT) iin = Iin_b[(size_t)(t + 1) * NH];

        // Recurrent input for NEXT step: sum of active rows of WrecT
        rec = 0.f;
        #pragma unroll 4
        for (int i = 0; i < total; ++i)
            rec += g_WrecT[s_list[i] * NH + h];

        // Output accumulator neurons
        if (h < NO) {
            float i2 = 0.f;
            #pragma unroll 4
            for (int i = 0; i < total; ++i)
                i2 += s_w2t[s_list[i] * 12 + h];
            v2 = fmaxf(v2 + i2 - OLEAK, 0.f);
            osum += v2;
        }
        __syncthreads();   // protect s_list / s_wcnt before next iteration
    }

    if (h < NO) out[b * NO + h] = osum * (1.0f / (float)NT);
}

// ---------------------------------------------------------------------------
extern "C" void kernel_launch(void* const* d_in, const int* in_sizes, int n_in,
                              void* d_out, int out_size) {
    const float* x     = (const float*)d_in[0];
    const float* w1    = (const float*)d_in[1];
    const float* w_rec = (const float*)d_in[2];
    const float* w2    = (const float*)d_in[3];
    float* out = (float*)d_out;

    prep_kernel<<<(NH * NH + 255) / 256, 256>>>(w_rec);

    dim3 gg(NH / BN, (NB * NT) / BM);   // (4, 128)
    gemm_kernel<<<gg, 256>>>(x, w1);

    snn_kernel<<<NB, NH>>>(w2, out);
}